// round 1
// baseline (speedup 1.0000x reference)
#include <cuda_runtime.h>
#include <cuda_bf16.h>

// Problem constants (GCN: 2-layer, N nodes, E edges)
#define NN     100000
#define INCH   500
#define HID    64
#define OUTC   40

// ---------------- scratch (static device globals: allowed) ----------------
__device__ float g_dinv[NN];                       // deg -> rsqrt(deg)
__device__ float g_XW[(size_t)NN * HID];           // x @ W_cons
__device__ float g_H [(size_t)NN * HID];           // aggregated layer-1 (pre-bias/relu)
__device__ float g_G [(size_t)NN * OUTC];          // relu(H+b) @ W_cls

// ---------------- degree / normalization ----------------
__global__ void k_init_deg() {
    int i = blockIdx.x * blockDim.x + threadIdx.x;
    if (i < NN) g_dinv[i] = 1.0f;   // self-loop contributes 1 to in-degree
}

__global__ void k_count_deg(const int* __restrict__ dst, int E) {
    int e = blockIdx.x * blockDim.x + threadIdx.x;
    if (e < E) atomicAdd(&g_dinv[dst[e]], 1.0f);
}

__global__ void k_rsqrt_deg() {
    int i = blockIdx.x * blockDim.x + threadIdx.x;
    if (i < NN) g_dinv[i] = rsqrtf(g_dinv[i]);   // deg >= 1 always
}

// ---------------- GEMM1: XW = x @ W_cons  [100000 x 500] @ [500 x 64] ----------------
// 64x64 output tile per block, K-tile 32, 256 threads, 4x4 micro-tile.
__global__ void k_gemm1(const float* __restrict__ X, const float* __restrict__ W) {
    __shared__ float As[32][68];   // [kk][row], padded: row-group float4 reads stay 16B aligned
    __shared__ float Bs[32][64];   // [kk][col]

    const int row0 = blockIdx.x * 64;
    const int tid  = threadIdx.x;
    const int tx   = tid & 15;     // col group
    const int ty   = tid >> 4;     // row group

    float acc[4][4];
#pragma unroll
    for (int i = 0; i < 4; i++)
#pragma unroll
        for (int j = 0; j < 4; j++) acc[i][j] = 0.0f;

    for (int k0 = 0; k0 < INCH; k0 += 32) {
        // load A tile: 64 rows x 32 k (coalesced along k)
#pragma unroll
        for (int i = tid; i < 64 * 32; i += 256) {
            int r  = i >> 5;
            int kk = i & 31;
            int gr = row0 + r;
            int gk = k0 + kk;
            As[kk][r] = (gr < NN && gk < INCH) ? X[(size_t)gr * INCH + gk] : 0.0f;
        }
        // load B tile: 32 k x 64 cols (coalesced along col)
#pragma unroll
        for (int i = tid; i < 32 * 64; i += 256) {
            int kk = i >> 6;
            int c  = i & 63;
            int gk = k0 + kk;
            Bs[kk][c] = (gk < INCH) ? W[(size_t)gk * HID + c] : 0.0f;
        }
        __syncthreads();

#pragma unroll
        for (int kk = 0; kk < 32; kk++) {
            float4 a4 = *reinterpret_cast<const float4*>(&As[kk][ty * 4]);
            float4 b4 = *reinterpret_cast<const float4*>(&Bs[kk][tx * 4]);
            float a[4] = {a4.x, a4.y, a4.z, a4.w};
            float b[4] = {b4.x, b4.y, b4.z, b4.w};
#pragma unroll
            for (int i = 0; i < 4; i++)
#pragma unroll
                for (int j = 0; j < 4; j++) acc[i][j] += a[i] * b[j];
        }
        __syncthreads();
    }

#pragma unroll
    for (int i = 0; i < 4; i++) {
        int gr = row0 + ty * 4 + i;
        if (gr < NN) {
            float4 v = make_float4(acc[i][0], acc[i][1], acc[i][2], acc[i][3]);
            *reinterpret_cast<float4*>(&g_XW[(size_t)gr * HID + tx * 4]) = v;
        }
    }
}

// ---------------- layer-1 aggregation ----------------
// init: self loop H[i] = dinv[i]^2 * XW[i]   (16 float4 per row)
__global__ void k_init_h() {
    int idx = blockIdx.x * blockDim.x + threadIdx.x;   // NN*16 float4 chunks
    if (idx < NN * 16) {
        int i = idx >> 4;
        float d = g_dinv[i];
        float w = d * d;
        float4 v = reinterpret_cast<const float4*>(g_XW)[idx];
        v.x *= w; v.y *= w; v.z *= w; v.w *= w;
        reinterpret_cast<float4*>(g_H)[idx] = v;
    }
}

__device__ __forceinline__ void red_add_v4(float* p, float a, float b, float c, float d) {
    asm volatile("red.global.add.v4.f32 [%0], {%1,%2,%3,%4};"
                 :: "l"(p), "f"(a), "f"(b), "f"(c), "f"(d) : "memory");
}

// scatter edges: H[dst] += w * XW[src].  4 threads/edge, 16 floats each.
__global__ void k_scatter1(const int* __restrict__ src, const int* __restrict__ dst, int E) {
    int idx = blockIdx.x * blockDim.x + threadIdx.x;
    if (idx >= E * 4) return;
    int e = idx >> 2;
    int c = (idx & 3) << 4;                  // 0,16,32,48
    int s = src[e];
    int d = dst[e];
    float w = g_dinv[s] * g_dinv[d];
    const float4* xs = reinterpret_cast<const float4*>(g_XW + (size_t)s * HID + c);
    float* hb = g_H + (size_t)d * HID + c;
#pragma unroll
    for (int j = 0; j < 4; j++) {
        float4 v = xs[j];
        red_add_v4(hb + j * 4, v.x * w, v.y * w, v.z * w, v.w * w);
    }
}

// ---------------- GEMM2: G = relu(H + b_cons) @ W_cls  [100000 x 64] @ [64 x 40] ----------------
// 64 rows per block, 320 threads: thread = (r in 0..7, c in 0..39), 8 rows each.
__global__ void k_gemm2(const float* __restrict__ Wc, const float* __restrict__ bc) {
    __shared__ float Hs[64][65];
    __shared__ float Ws[64][40];

    const int row0 = blockIdx.x * 64;
    const int tid  = threadIdx.x;

    for (int i = tid; i < 64 * 64; i += 320) {
        int r = i >> 6, k = i & 63;
        int gr = row0 + r;
        float v = 0.0f;
        if (gr < NN) v = g_H[(size_t)gr * HID + k] + bc[k];
        Hs[r][k] = fmaxf(v, 0.0f);
    }
    for (int i = tid; i < 64 * 40; i += 320) {
        int k = i / 40, c = i - k * 40;
        Ws[k][c] = Wc[(size_t)k * OUTC + c];
    }
    __syncthreads();

    const int r = tid / 40;        // 0..7
    const int c = tid - r * 40;    // 0..39
    float acc[8];
#pragma unroll
    for (int j = 0; j < 8; j++) acc[j] = 0.0f;

#pragma unroll
    for (int k = 0; k < 64; k++) {
        float w = Ws[k][c];
#pragma unroll
        for (int j = 0; j < 8; j++) acc[j] += Hs[r + j * 8][k] * w;
    }

#pragma unroll
    for (int j = 0; j < 8; j++) {
        int gr = row0 + r + j * 8;
        if (gr < NN) g_G[(size_t)gr * OUTC + c] = acc[j];
    }
}

// ---------------- layer-2 aggregation ----------------
// init: out[i] = dinv[i]^2 * G[i] + b_cls
__global__ void k_init_out(float* __restrict__ out, const float* __restrict__ bcls) {
    int idx = blockIdx.x * blockDim.x + threadIdx.x;   // NN*40
    if (idx < NN * OUTC) {
        int i = idx / OUTC;
        int c = idx - i * OUTC;
        float d = g_dinv[i];
        out[idx] = d * d * g_G[idx] + bcls[c];
    }
}

// scatter edges: out[dst] += w * G[src].  5 threads/edge, 8 floats each.
__global__ void k_scatter2(const int* __restrict__ src, const int* __restrict__ dst, int E,
                           float* __restrict__ out) {
    int idx = blockIdx.x * blockDim.x + threadIdx.x;
    if (idx >= E * 5) return;
    int e  = idx / 5;
    int ch = idx - e * 5;
    int c  = ch * 8;                         // 0,8,16,24,32
    int s = src[e];
    int d = dst[e];
    float w = g_dinv[s] * g_dinv[d];
    const float4* xs = reinterpret_cast<const float4*>(g_G + (size_t)s * OUTC + c);
    float* ob = out + (size_t)d * OUTC + c;
#pragma unroll
    for (int j = 0; j < 2; j++) {
        float4 v = xs[j];
        red_add_v4(ob + j * 4, v.x * w, v.y * w, v.z * w, v.w * w);
    }
}

// ---------------- launch ----------------
extern "C" void kernel_launch(void* const* d_in, const int* in_sizes, int n_in,
                              void* d_out, int out_size) {
    const float* x     = (const float*)d_in[0];
    const int*   ei    = (const int*)  d_in[1];
    const float* Wcons = (const float*)d_in[2];
    const float* bcons = (const float*)d_in[3];
    const float* Wcls  = (const float*)d_in[4];
    const float* bcls  = (const float*)d_in[5];
    const int E = in_sizes[1] / 2;
    const int* src = ei;
    const int* dst = ei + E;
    float* out = (float*)d_out;

    k_init_deg <<<(NN + 255) / 256, 256>>>();
    k_count_deg<<<(E + 255) / 256, 256>>>(dst, E);
    k_rsqrt_deg<<<(NN + 255) / 256, 256>>>();

    k_gemm1    <<<(NN + 63) / 64, 256>>>(x, Wcons);
    k_init_h   <<<(NN * 16 + 255) / 256, 256>>>();
    k_scatter1 <<<((size_t)E * 4 + 255) / 256, 256>>>(src, dst, E);

    k_gemm2    <<<(NN + 63) / 64, 320>>>(Wcls, bcons);
    k_init_out <<<(NN * OUTC + 255) / 256, 256>>>(out, bcls);
    k_scatter2 <<<((size_t)E * 5 + 255) / 256, 256>>>(src, dst, E, out);
}

// round 2
// speedup vs baseline: 1.7071x; 1.7071x over previous
#include <cuda_runtime.h>
#include <cuda_bf16.h>

#define NN    100000
#define INCH  500
#define HID   64
#define OUTC  40
#define EMAX  3200000
#define NB    ((NN + 255) / 256)   // scan blocks = 391

// ---------------- scratch (device globals) ----------------
__device__ float g_dinv[NN];
__device__ int   g_cnt[NN];
__device__ int   g_off[NN + 1];
__device__ int   g_cur[NN];
__device__ int   g_bsum[512];
__device__ int   g_bscan[512];
__device__ int2  g_epk[EMAX];                 // (src, bitcast(weight)) grouped by dst
__device__ float g_XW[(size_t)NN * HID];      // x @ W_cons
__device__ float g_H [(size_t)NN * HID];      // relu(agg1 + b_cons)
__device__ float g_G [(size_t)NN * OUTC];     // H @ W_cls

// ---------------- degree / dinv ----------------
__global__ void k_zero_cnt() {
    int i = blockIdx.x * blockDim.x + threadIdx.x;
    if (i < NN) g_cnt[i] = 0;
}
__global__ void k_count(const int* __restrict__ dst, int E) {
    int e = blockIdx.x * blockDim.x + threadIdx.x;
    if (e < E) atomicAdd(&g_cnt[dst[e]], 1);
}
__global__ void k_dinv() {
    int i = blockIdx.x * blockDim.x + threadIdx.x;
    if (i < NN) g_dinv[i] = rsqrtf((float)(g_cnt[i] + 1));   // +1 self loop
}

// ---------------- 2-level exclusive scan over g_cnt -> g_off ----------------
__global__ void k_scan_block() {
    __shared__ int sh[256];
    int b = blockIdx.x, t = threadIdx.x;
    int i = b * 256 + t;
    int v = (i < NN) ? g_cnt[i] : 0;
    int x = v;
    sh[t] = x; __syncthreads();
#pragma unroll
    for (int d = 1; d < 256; d <<= 1) {
        int y = (t >= d) ? sh[t - d] : 0;
        __syncthreads();
        x += y; sh[t] = x;
        __syncthreads();
    }
    if (i < NN) g_off[i] = x - v;
    if (t == 255) g_bsum[b] = x;
}
__global__ void k_scan_tops() {
    __shared__ int sh[512];
    int t = threadIdx.x;
    int v = (t < NB) ? g_bsum[t] : 0;
    int x = v;
    sh[t] = x; __syncthreads();
#pragma unroll
    for (int d = 1; d < 512; d <<= 1) {
        int y = (t >= d) ? sh[t - d] : 0;
        __syncthreads();
        x += y; sh[t] = x;
        __syncthreads();
    }
    if (t < NB) g_bscan[t] = x - v;
}
__global__ void k_scan_add(int E) {
    int i = blockIdx.x * blockDim.x + threadIdx.x;
    if (i < NN) {
        g_off[i] += g_bscan[i >> 8];
        g_cur[i] = 0;
    }
    if (i == 0) g_off[NN] = E;
}

// ---------------- CSR fill: group edges by dst ----------------
__global__ void k_fill(const int* __restrict__ src, const int* __restrict__ dst, int E) {
    int e = blockIdx.x * blockDim.x + threadIdx.x;
    if (e >= E) return;
    int s = src[e];
    int d = dst[e];
    int pos = g_off[d] + atomicAdd(&g_cur[d], 1);
    g_epk[pos] = make_int2(s, __float_as_int(g_dinv[s] * g_dinv[d]));
}

// ---------------- GEMM1: XW = x @ W_cons  [100000 x 500] @ [500 x 64] ----------------
// 128x64 block tile, 256 threads, 8x4 micro-tile, K-tile 32.
__global__ void __launch_bounds__(256) k_gemm1(const float* __restrict__ X,
                                               const float* __restrict__ W) {
    __shared__ float As[32][132];   // [kk][row], pad 4
    __shared__ float Bs[32][64];    // [kk][col]

    const int row0 = blockIdx.x * 128;
    const int tid  = threadIdx.x;
    const int tx   = tid & 15;      // col group: cols tx*4 .. tx*4+3
    const int ty   = tid >> 4;      // row group: rows ty*8 .. ty*8+7

    float acc[8][4];
#pragma unroll
    for (int i = 0; i < 8; i++)
#pragma unroll
        for (int j = 0; j < 4; j++) acc[i][j] = 0.0f;

    for (int k0 = 0; k0 < INCH; k0 += 32) {
        const bool full = (k0 + 32 <= INCH);
        if (full) {
            // A tile: 128 rows x 32 k, float4 along k. 1024 float4s / 256 thr = 4 each.
#pragma unroll
            for (int i = tid; i < 128 * 8; i += 256) {
                int r  = i >> 3;          // 0..127
                int q  = i & 7;           // float4 index along k
                int gr = row0 + r;
                float4 v = (gr < NN)
                    ? *reinterpret_cast<const float4*>(X + (size_t)gr * INCH + k0 + q * 4)
                    : make_float4(0.f, 0.f, 0.f, 0.f);
                As[q * 4 + 0][r] = v.x;
                As[q * 4 + 1][r] = v.y;
                As[q * 4 + 2][r] = v.z;
                As[q * 4 + 3][r] = v.w;
            }
            // B tile: 32 k x 64 cols, float4 along col. 512 float4s / 256 thr = 2 each.
#pragma unroll
            for (int i = tid; i < 32 * 16; i += 256) {
                int kk = i >> 4;
                int q  = i & 15;
                float4 v = *reinterpret_cast<const float4*>(W + (size_t)(k0 + kk) * HID + q * 4);
                *reinterpret_cast<float4*>(&Bs[kk][q * 4]) = v;
            }
        } else {
            // tail tile (k0=480, 20 valid k): guarded scalar loads
#pragma unroll
            for (int i = tid; i < 128 * 32; i += 256) {
                int r  = i >> 5;
                int kk = i & 31;
                int gr = row0 + r;
                int gk = k0 + kk;
                As[kk][r] = (gr < NN && gk < INCH) ? X[(size_t)gr * INCH + gk] : 0.0f;
            }
#pragma unroll
            for (int i = tid; i < 32 * 64; i += 256) {
                int kk = i >> 6;
                int c  = i & 63;
                int gk = k0 + kk;
                Bs[kk][c] = (gk < INCH) ? W[(size_t)gk * HID + c] : 0.0f;
            }
        }
        __syncthreads();

#pragma unroll
        for (int kk = 0; kk < 32; kk++) {
            float4 a0 = *reinterpret_cast<const float4*>(&As[kk][ty * 8]);
            float4 a1 = *reinterpret_cast<const float4*>(&As[kk][ty * 8 + 4]);
            float4 b4 = *reinterpret_cast<const float4*>(&Bs[kk][tx * 4]);
            float a[8] = {a0.x, a0.y, a0.z, a0.w, a1.x, a1.y, a1.z, a1.w};
            float b[4] = {b4.x, b4.y, b4.z, b4.w};
#pragma unroll
            for (int i = 0; i < 8; i++)
#pragma unroll
                for (int j = 0; j < 4; j++) acc[i][j] += a[i] * b[j];
        }
        __syncthreads();
    }

#pragma unroll
    for (int i = 0; i < 8; i++) {
        int gr = row0 + ty * 8 + i;
        if (gr < NN) {
            float4 v = make_float4(acc[i][0], acc[i][1], acc[i][2], acc[i][3]);
            *reinterpret_cast<float4*>(&g_XW[(size_t)gr * HID + tx * 4]) = v;
        }
    }
}

// ---------------- layer-1 aggregation: warp per node, fused bias+relu ----------------
__global__ void k_agg1(const float* __restrict__ bcons) {
    int warp = (blockIdx.x * blockDim.x + threadIdx.x) >> 5;
    int lane = threadIdx.x & 31;
    if (warp >= NN) return;
    const int node = warp;
    const int beg = g_off[node];
    const int end = g_off[node + 1];

    float dd = g_dinv[node]; dd *= dd;
    float2 v0 = *reinterpret_cast<const float2*>(g_XW + (size_t)node * HID + 2 * lane);
    float2 acc = make_float2(dd * v0.x, dd * v0.y);

    for (int i = beg; i < end; i += 8) {
        int2 ep = make_int2(0, 0);
        int idx = i + lane;
        if (lane < 8 && idx < end) ep = g_epk[idx];
#pragma unroll
        for (int j = 0; j < 8; j++) {
            int sj = __shfl_sync(0xffffffffu, ep.x, j);
            int wb = __shfl_sync(0xffffffffu, ep.y, j);
            if (i + j < end) {
                float wj = __int_as_float(wb);
                float2 v = *reinterpret_cast<const float2*>(g_XW + (size_t)sj * HID + 2 * lane);
                acc.x += wj * v.x;
                acc.y += wj * v.y;
            }
        }
    }
    float2 b = *reinterpret_cast<const float2*>(bcons + 2 * lane);
    acc.x = fmaxf(acc.x + b.x, 0.0f);
    acc.y = fmaxf(acc.y + b.y, 0.0f);
    *reinterpret_cast<float2*>(g_H + (size_t)node * HID + 2 * lane) = acc;
}

// ---------------- GEMM2: G = H @ W_cls  [100000 x 64] @ [64 x 40] ----------------
__global__ void __launch_bounds__(320) k_gemm2(const float* __restrict__ Wc) {
    __shared__ float Hs[64][65];
    __shared__ float Ws[64][40];

    const int row0 = blockIdx.x * 64;
    const int tid  = threadIdx.x;

    for (int i = tid; i < 64 * 64; i += 320) {
        int r = i >> 6, k = i & 63;
        int gr = row0 + r;
        Hs[r][k] = (gr < NN) ? g_H[(size_t)gr * HID + k] : 0.0f;
    }
    for (int i = tid; i < 64 * 40; i += 320) {
        int k = i / 40, c = i - k * 40;
        Ws[k][c] = Wc[(size_t)k * OUTC + c];
    }
    __syncthreads();

    const int r = tid / 40;
    const int c = tid - r * 40;
    float acc[8];
#pragma unroll
    for (int j = 0; j < 8; j++) acc[j] = 0.0f;

#pragma unroll
    for (int k = 0; k < 64; k++) {
        float w = Ws[k][c];
#pragma unroll
        for (int j = 0; j < 8; j++) acc[j] += Hs[r + j * 8][k] * w;
    }
#pragma unroll
    for (int j = 0; j < 8; j++) {
        int gr = row0 + r + j * 8;
        if (gr < NN) g_G[(size_t)gr * OUTC + c] = acc[j];
    }
}

// ---------------- layer-2 aggregation: warp per node, fused b_cls ----------------
__global__ void k_agg2(float* __restrict__ out, const float* __restrict__ bcls) {
    int warp = (blockIdx.x * blockDim.x + threadIdx.x) >> 5;
    int lane = threadIdx.x & 31;
    if (warp >= NN) return;
    const int node = warp;
    const int beg = g_off[node];
    const int end = g_off[node + 1];

    float dd = g_dinv[node]; dd *= dd;
    const float* grow0 = g_G + (size_t)node * OUTC;
    float a0 = dd * grow0[lane];
    float a1 = (lane < 8) ? dd * grow0[32 + lane] : 0.0f;

    for (int i = beg; i < end; i += 8) {
        int2 ep = make_int2(0, 0);
        int idx = i + lane;
        if (lane < 8 && idx < end) ep = g_epk[idx];
#pragma unroll
        for (int j = 0; j < 8; j++) {
            int sj = __shfl_sync(0xffffffffu, ep.x, j);
            int wb = __shfl_sync(0xffffffffu, ep.y, j);
            if (i + j < end) {
                float wj = __int_as_float(wb);
                const float* grow = g_G + (size_t)sj * OUTC;
                a0 += wj * grow[lane];
                if (lane < 8) a1 += wj * grow[32 + lane];
            }
        }
    }
    out[(size_t)node * OUTC + lane] = a0 + bcls[lane];
    if (lane < 8) out[(size_t)node * OUTC + 32 + lane] = a1 + bcls[32 + lane];
}

// ---------------- launch ----------------
extern "C" void kernel_launch(void* const* d_in, const int* in_sizes, int n_in,
                              void* d_out, int out_size) {
    const float* x     = (const float*)d_in[0];
    const int*   ei    = (const int*)  d_in[1];
    const float* Wcons = (const float*)d_in[2];
    const float* bcons = (const float*)d_in[3];
    const float* Wcls  = (const float*)d_in[4];
    const float* bcls  = (const float*)d_in[5];
    const int E = in_sizes[1] / 2;
    const int* src = ei;
    const int* dst = ei + E;
    float* out = (float*)d_out;

    // degree + normalization
    k_zero_cnt<<<NB, 256>>>();
    k_count   <<<(E + 255) / 256, 256>>>(dst, E);
    k_dinv    <<<NB, 256>>>();

    // CSR build
    k_scan_block<<<NB, 256>>>();
    k_scan_tops <<<1, 512>>>();
    k_scan_add  <<<NB, 256>>>(E);
    k_fill      <<<(E + 255) / 256, 256>>>(src, dst, E);

    // layer 1
    k_gemm1<<<(NN + 127) / 128, 256>>>(x, Wcons);
    k_agg1 <<<(NN * 32 + 255) / 256, 256>>>(bcons);

    // layer 2
    k_gemm2<<<(NN + 63) / 64, 320>>>(Wcls);
    k_agg2 <<<(NN * 32 + 255) / 256, 256>>>(out, bcls);
}

// round 3
// speedup vs baseline: 1.9330x; 1.1323x over previous
#include <cuda_runtime.h>
#include <cuda_bf16.h>
#include <cstdint>

#define NN    100000
#define INCH  500
#define HID   64
#define OUTC  40
#define EMAX  3200000
#define NB    ((NN + 255) / 256)   // scan blocks = 391

// ---------------- scratch (device globals) ----------------
__device__ float g_dinv[NN];
__device__ int   g_cnt[NN];
__device__ int   g_off[NN + 1];
__device__ int   g_cur[NN];
__device__ int   g_bsum[512];
__device__ int   g_bscan[512];
__device__ int2  g_epk[EMAX];                 // (src, bitcast(weight)) grouped by dst
__device__ float g_XW[(size_t)NN * HID];      // x @ W_cons
__device__ float g_H [(size_t)NN * HID];      // relu(agg1 + b_cons)
__device__ float g_G [(size_t)NN * OUTC];     // H @ W_cls

// ---------------- degree count ----------------
__global__ void k_count(const int* __restrict__ dst, int E) {
    int e = blockIdx.x * blockDim.x + threadIdx.x;
    if (e < E) atomicAdd(&g_cnt[dst[e]], 1);
}

// ---------------- 2-level exclusive scan over g_cnt -> g_off (dinv fused) ----------------
__global__ void k_scan_block() {
    __shared__ int sh[256];
    int b = blockIdx.x, t = threadIdx.x;
    int i = b * 256 + t;
    int v = (i < NN) ? g_cnt[i] : 0;
    if (i < NN) g_dinv[i] = rsqrtf((float)(v + 1));   // +1 self loop
    int x = v;
    sh[t] = x; __syncthreads();
#pragma unroll
    for (int d = 1; d < 256; d <<= 1) {
        int y = (t >= d) ? sh[t - d] : 0;
        __syncthreads();
        x += y; sh[t] = x;
        __syncthreads();
    }
    if (i < NN) g_off[i] = x - v;
    if (t == 255) g_bsum[b] = x;
}
__global__ void k_scan_tops() {
    __shared__ int sh[512];
    int t = threadIdx.x;
    int v = (t < NB) ? g_bsum[t] : 0;
    int x = v;
    sh[t] = x; __syncthreads();
#pragma unroll
    for (int d = 1; d < 512; d <<= 1) {
        int y = (t >= d) ? sh[t - d] : 0;
        __syncthreads();
        x += y; sh[t] = x;
        __syncthreads();
    }
    if (t < NB) g_bscan[t] = x - v;
}
__global__ void k_scan_add(int E) {
    int i = blockIdx.x * blockDim.x + threadIdx.x;
    if (i < NN) {
        g_off[i] += g_bscan[i >> 8];
        g_cur[i] = 0;
    }
    if (i == 0) g_off[NN] = E;
}

// ---------------- CSR fill: group edges by dst ----------------
__global__ void k_fill(const int* __restrict__ src, const int* __restrict__ dst, int E) {
    int e = blockIdx.x * blockDim.x + threadIdx.x;
    if (e >= E) return;
    int s = src[e];
    int d = dst[e];
    int pos = g_off[d] + atomicAdd(&g_cur[d], 1);
    g_epk[pos] = make_int2(s, __float_as_int(g_dinv[s] * g_dinv[d]));
}

// ---------------- GEMM1 (tf32 tensor cores): XW = x @ W_cons ----------------
// [100000 x 500] @ [500 x 64]; 128x64 block tile, 256 thr = 8 warps (4M x 2N),
// warp tile 32x32 via mma.sync.m16n8k8.tf32 (2 M-tiles x 4 N-tiles).
__device__ __forceinline__ uint32_t f2tf32(float f) {
    uint32_t r;
    asm("cvt.rna.tf32.f32 %0, %1;" : "=r"(r) : "f"(f));
    return r;
}
__device__ __forceinline__ void mma_tf32(float* d, const uint32_t* a, const uint32_t* b) {
    asm volatile(
        "mma.sync.aligned.m16n8k8.row.col.f32.tf32.tf32.f32 "
        "{%0,%1,%2,%3}, {%4,%5,%6,%7}, {%8,%9}, {%0,%1,%2,%3};"
        : "+f"(d[0]), "+f"(d[1]), "+f"(d[2]), "+f"(d[3])
        : "r"(a[0]), "r"(a[1]), "r"(a[2]), "r"(a[3]), "r"(b[0]), "r"(b[1]));
}

__global__ void __launch_bounds__(256) k_gemm1(const float* __restrict__ X,
                                               const float* __restrict__ W) {
    __shared__ uint32_t As[32][132];   // [kk][row] tf32 bits, pad 4
    __shared__ uint32_t Bs[32][68];    // [kk][col] tf32 bits, pad 4

    const int row0 = blockIdx.x * 128;
    const int tid  = threadIdx.x;
    const int lane = tid & 31;
    const int wid  = tid >> 5;
    const int wm   = wid & 3;          // warp row group (32 rows)
    const int wn   = wid >> 2;         // warp col group (32 cols)
    const int g    = lane >> 2;        // 0..7
    const int q4   = lane & 3;         // 0..3

    float acc[2][4][4];
#pragma unroll
    for (int tm = 0; tm < 2; tm++)
#pragma unroll
        for (int tn = 0; tn < 4; tn++)
#pragma unroll
            for (int j = 0; j < 4; j++) acc[tm][tn][j] = 0.0f;

    for (int k0 = 0; k0 < INCH; k0 += 32) {
        const bool full = (k0 + 32 <= INCH);
        if (full) {
            // A tile: 128 rows x 32 k, float4 along k
#pragma unroll
            for (int i = tid; i < 128 * 8; i += 256) {
                int r  = i >> 3;
                int q  = i & 7;
                int gr = row0 + r;
                float4 v = (gr < NN)
                    ? *reinterpret_cast<const float4*>(X + (size_t)gr * INCH + k0 + q * 4)
                    : make_float4(0.f, 0.f, 0.f, 0.f);
                As[q * 4 + 0][r] = f2tf32(v.x);
                As[q * 4 + 1][r] = f2tf32(v.y);
                As[q * 4 + 2][r] = f2tf32(v.z);
                As[q * 4 + 3][r] = f2tf32(v.w);
            }
            // B tile: 32 k x 64 cols, float4 along col
#pragma unroll
            for (int i = tid; i < 32 * 16; i += 256) {
                int kk = i >> 4;
                int q  = i & 15;
                float4 v = *reinterpret_cast<const float4*>(W + (size_t)(k0 + kk) * HID + q * 4);
                Bs[kk][q * 4 + 0] = f2tf32(v.x);
                Bs[kk][q * 4 + 1] = f2tf32(v.y);
                Bs[kk][q * 4 + 2] = f2tf32(v.z);
                Bs[kk][q * 4 + 3] = f2tf32(v.w);
            }
        } else {
            // tail tile (k0=480, 20 valid k): guarded scalar loads, zero pad
#pragma unroll
            for (int i = tid; i < 128 * 32; i += 256) {
                int r  = i >> 5;
                int kk = i & 31;
                int gr = row0 + r;
                int gk = k0 + kk;
                float v = (gr < NN && gk < INCH) ? X[(size_t)gr * INCH + gk] : 0.0f;
                As[kk][r] = f2tf32(v);
            }
#pragma unroll
            for (int i = tid; i < 32 * 64; i += 256) {
                int kk = i >> 6;
                int c  = i & 63;
                int gk = k0 + kk;
                float v = (gk < INCH) ? W[(size_t)gk * HID + c] : 0.0f;
                Bs[kk][c] = f2tf32(v);
            }
        }
        __syncthreads();

#pragma unroll
        for (int ks = 0; ks < 4; ks++) {
            const int kk = ks * 8 + q4;
            uint32_t a[2][4];
#pragma unroll
            for (int tm = 0; tm < 2; tm++) {
                int r = wm * 32 + tm * 16 + g;
                a[tm][0] = As[kk][r];
                a[tm][1] = As[kk][r + 8];
                a[tm][2] = As[kk + 4][r];
                a[tm][3] = As[kk + 4][r + 8];
            }
            uint32_t b[4][2];
#pragma unroll
            for (int tn = 0; tn < 4; tn++) {
                int c = wn * 32 + tn * 8 + g;
                b[tn][0] = Bs[kk][c];
                b[tn][1] = Bs[kk + 4][c];
            }
#pragma unroll
            for (int tm = 0; tm < 2; tm++)
#pragma unroll
                for (int tn = 0; tn < 4; tn++)
                    mma_tf32(acc[tm][tn], a[tm], b[tn]);
        }
        __syncthreads();
    }

    // epilogue: D frag rows g/g+8, cols q4*2 + {0,1}
#pragma unroll
    for (int tm = 0; tm < 2; tm++) {
#pragma unroll
        for (int tn = 0; tn < 4; tn++) {
            int c = wn * 32 + tn * 8 + q4 * 2;
            int r = row0 + wm * 32 + tm * 16 + g;
            if (r < NN)
                *reinterpret_cast<float2*>(&g_XW[(size_t)r * HID + c]) =
                    make_float2(acc[tm][tn][0], acc[tm][tn][1]);
            if (r + 8 < NN)
                *reinterpret_cast<float2*>(&g_XW[(size_t)(r + 8) * HID + c]) =
                    make_float2(acc[tm][tn][2], acc[tm][tn][3]);
        }
    }
}

// ---------------- layer-1 aggregation: warp per node, fused bias+relu ----------------
__global__ void k_agg1(const float* __restrict__ bcons) {
    int warp = (blockIdx.x * blockDim.x + threadIdx.x) >> 5;
    int lane = threadIdx.x & 31;
    if (warp >= NN) return;
    const int node = warp;
    const int beg = g_off[node];
    const int end = g_off[node + 1];

    float dd = g_dinv[node]; dd *= dd;
    float2 v0 = *reinterpret_cast<const float2*>(g_XW + (size_t)node * HID + 2 * lane);
    float2 acc = make_float2(dd * v0.x, dd * v0.y);

    for (int i = beg; i < end; i += 8) {
        int2 ep = make_int2(0, 0);
        int idx = i + lane;
        if (lane < 8 && idx < end) ep = g_epk[idx];
#pragma unroll
        for (int j = 0; j < 8; j++) {
            int sj = __shfl_sync(0xffffffffu, ep.x, j);
            int wb = __shfl_sync(0xffffffffu, ep.y, j);
            if (i + j < end) {
                float wj = __int_as_float(wb);
                float2 v = *reinterpret_cast<const float2*>(g_XW + (size_t)sj * HID + 2 * lane);
                acc.x += wj * v.x;
                acc.y += wj * v.y;
            }
        }
    }
    float2 b = *reinterpret_cast<const float2*>(bcons + 2 * lane);
    acc.x = fmaxf(acc.x + b.x, 0.0f);
    acc.y = fmaxf(acc.y + b.y, 0.0f);
    *reinterpret_cast<float2*>(g_H + (size_t)node * HID + 2 * lane) = acc;
}

// ---------------- GEMM2: G = H @ W_cls  [100000 x 64] @ [64 x 40] ----------------
__global__ void __launch_bounds__(320) k_gemm2(const float* __restrict__ Wc) {
    __shared__ float Hs[64][65];
    __shared__ float Ws[64][40];

    const int row0 = blockIdx.x * 64;
    const int tid  = threadIdx.x;

    for (int i = tid; i < 64 * 64; i += 320) {
        int r = i >> 6, k = i & 63;
        int gr = row0 + r;
        Hs[r][k] = (gr < NN) ? g_H[(size_t)gr * HID + k] : 0.0f;
    }
    for (int i = tid; i < 64 * 40; i += 320) {
        int k = i / 40, c = i - k * 40;
        Ws[k][c] = Wc[(size_t)k * OUTC + c];
    }
    __syncthreads();

    const int r = tid / 40;
    const int c = tid - r * 40;
    float acc[8];
#pragma unroll
    for (int j = 0; j < 8; j++) acc[j] = 0.0f;

#pragma unroll
    for (int k = 0; k < 64; k++) {
        float w = Ws[k][c];
#pragma unroll
        for (int j = 0; j < 8; j++) acc[j] += Hs[r + j * 8][k] * w;
    }
#pragma unroll
    for (int j = 0; j < 8; j++) {
        int gr = row0 + r + j * 8;
        if (gr < NN) g_G[(size_t)gr * OUTC + c] = acc[j];
    }
}

// ---------------- layer-2 aggregation: warp per node, fused b_cls ----------------
__global__ void k_agg2(float* __restrict__ out, const float* __restrict__ bcls) {
    int warp = (blockIdx.x * blockDim.x + threadIdx.x) >> 5;
    int lane = threadIdx.x & 31;
    if (warp >= NN) return;
    const int node = warp;
    const int beg = g_off[node];
    const int end = g_off[node + 1];

    float dd = g_dinv[node]; dd *= dd;
    const float* grow0 = g_G + (size_t)node * OUTC;
    float a0 = dd * grow0[lane];
    float a1 = (lane < 8) ? dd * grow0[32 + lane] : 0.0f;

    for (int i = beg; i < end; i += 8) {
        int2 ep = make_int2(0, 0);
        int idx = i + lane;
        if (lane < 8 && idx < end) ep = g_epk[idx];
#pragma unroll
        for (int j = 0; j < 8; j++) {
            int sj = __shfl_sync(0xffffffffu, ep.x, j);
            int wb = __shfl_sync(0xffffffffu, ep.y, j);
            if (i + j < end) {
                float wj = __int_as_float(wb);
                const float* grow = g_G + (size_t)sj * OUTC;
                a0 += wj * grow[lane];
                if (lane < 8) a1 += wj * grow[32 + lane];
            }
        }
    }
    out[(size_t)node * OUTC + lane] = a0 + bcls[lane];
    if (lane < 8) out[(size_t)node * OUTC + 32 + lane] = a1 + bcls[32 + lane];
}

// ---------------- launch ----------------
extern "C" void kernel_launch(void* const* d_in, const int* in_sizes, int n_in,
                              void* d_out, int out_size) {
    const float* x     = (const float*)d_in[0];
    const int*   ei    = (const int*)  d_in[1];
    const float* Wcons = (const float*)d_in[2];
    const float* bcons = (const float*)d_in[3];
    const float* Wcls  = (const float*)d_in[4];
    const float* bcls  = (const float*)d_in[5];
    const int E = in_sizes[1] / 2;
    const int* src = ei;
    const int* dst = ei + E;
    float* out = (float*)d_out;

    // degree count (memset node is graph-capturable)
    void* cntp = nullptr;
    cudaGetSymbolAddress(&cntp, g_cnt);
    cudaMemsetAsync(cntp, 0, NN * sizeof(int));
    k_count<<<(E + 255) / 256, 256>>>(dst, E);

    // CSR build (dinv fused into scan)
    k_scan_block<<<NB, 256>>>();
    k_scan_tops <<<1, 512>>>();
    k_scan_add  <<<NB, 256>>>(E);
    k_fill      <<<(E + 255) / 256, 256>>>(src, dst, E);

    // layer 1
    k_gemm1<<<(NN + 127) / 128, 256>>>(x, Wcons);
    k_agg1 <<<(NN * 32 + 255) / 256, 256>>>(bcons);

    // layer 2
    k_gemm2<<<(NN + 63) / 64, 320>>>(Wcls);
    k_agg2 <<<(NN * 32 + 255) / 256, 256>>>(out, bcls);
}

// round 4
// speedup vs baseline: 2.2609x; 1.1696x over previous
#include <cuda_runtime.h>
#include <cuda_bf16.h>
#include <cstdint>

#define NN    100000
#define INCH  500
#define HID   64
#define OUTC  40
#define EMAX  3200000
#define NB    ((NN + 255) / 256)   // scan blocks = 391

// ---------------- scratch (device globals) ----------------
__device__ float g_dinv[NN];
__device__ int   g_cnt[NN];
__device__ int   g_off[NN + 1];
__device__ int   g_cur[NN];
__device__ int   g_bsum[512];
__device__ int   g_bscan[512];
__device__ int2  g_epk[EMAX];                 // (src, bitcast(weight)) grouped by dst
__device__ float g_XW[(size_t)NN * HID];      // x @ W_cons
__device__ float g_H [(size_t)NN * HID];      // relu(agg1 + b_cons)
__device__ float g_G [(size_t)NN * OUTC];     // H @ W_cls

// ---------------- degree count ----------------
__global__ void k_count(const int* __restrict__ dst, int E) {
    int e = blockIdx.x * blockDim.x + threadIdx.x;
    if (e < E) atomicAdd(&g_cnt[dst[e]], 1);
}

// ---------------- 2-level exclusive scan over g_cnt -> g_off (dinv fused) ----------------
__global__ void k_scan_block() {
    __shared__ int sh[256];
    int b = blockIdx.x, t = threadIdx.x;
    int i = b * 256 + t;
    int v = (i < NN) ? g_cnt[i] : 0;
    if (i < NN) g_dinv[i] = rsqrtf((float)(v + 1));   // +1 self loop
    int x = v;
    sh[t] = x; __syncthreads();
#pragma unroll
    for (int d = 1; d < 256; d <<= 1) {
        int y = (t >= d) ? sh[t - d] : 0;
        __syncthreads();
        x += y; sh[t] = x;
        __syncthreads();
    }
    if (i < NN) g_off[i] = x - v;
    if (t == 255) g_bsum[b] = x;
}
__global__ void k_scan_tops() {
    __shared__ int sh[512];
    int t = threadIdx.x;
    int v = (t < NB) ? g_bsum[t] : 0;
    int x = v;
    sh[t] = x; __syncthreads();
#pragma unroll
    for (int d = 1; d < 512; d <<= 1) {
        int y = (t >= d) ? sh[t - d] : 0;
        __syncthreads();
        x += y; sh[t] = x;
        __syncthreads();
    }
    if (t < NB) g_bscan[t] = x - v;
}
__global__ void k_scan_add(int E) {
    int i = blockIdx.x * blockDim.x + threadIdx.x;
    if (i < NN) {
        g_off[i] += g_bscan[i >> 8];
        g_cur[i] = 0;
    }
    if (i == 0) g_off[NN] = E;
}

// ---------------- CSR fill: group edges by dst ----------------
__global__ void k_fill(const int* __restrict__ src, const int* __restrict__ dst, int E) {
    int e = blockIdx.x * blockDim.x + threadIdx.x;
    if (e >= E) return;
    int s = src[e];
    int d = dst[e];
    int pos = g_off[d] + atomicAdd(&g_cur[d], 1);
    g_epk[pos] = make_int2(s, __float_as_int(g_dinv[s] * g_dinv[d]));
}

// ---------------- GEMM1 (tf32 tensor cores, sw-pipelined): XW = x @ W_cons ----------------
__device__ __forceinline__ uint32_t f2tf32(float f) {
    uint32_t r;
    asm("cvt.rna.tf32.f32 %0, %1;" : "=r"(r) : "f"(f));
    return r;
}
__device__ __forceinline__ void mma_tf32(float* d, const uint32_t* a, const uint32_t* b) {
    asm volatile(
        "mma.sync.aligned.m16n8k8.row.col.f32.tf32.tf32.f32 "
        "{%0,%1,%2,%3}, {%4,%5,%6,%7}, {%8,%9}, {%0,%1,%2,%3};"
        : "+f"(d[0]), "+f"(d[1]), "+f"(d[2]), "+f"(d[3])
        : "r"(a[0]), "r"(a[1]), "r"(a[2]), "r"(a[3]), "r"(b[0]), "r"(b[1]));
}

__device__ __forceinline__ void g1_load(const float* __restrict__ X,
                                        const float* __restrict__ W,
                                        int row0, int k0, int tid,
                                        float4 aR[4], float4 bR[2]) {
    const int kq = (INCH - k0 >= 32) ? 8 : (INCH - k0) / 4;   // valid float4s along k (8 or 5)
#pragma unroll
    for (int n = 0; n < 4; n++) {
        int i = tid + n * 256;
        int r = i >> 3, q = i & 7;
        int gr = row0 + r;
        aR[n] = (gr < NN && q < kq)
            ? *reinterpret_cast<const float4*>(X + (size_t)gr * INCH + k0 + q * 4)
            : make_float4(0.f, 0.f, 0.f, 0.f);
    }
#pragma unroll
    for (int n = 0; n < 2; n++) {
        int i = tid + n * 256;
        int kk = i >> 4, q = i & 15;
        bR[n] = (k0 + kk < INCH)
            ? *reinterpret_cast<const float4*>(W + (size_t)(k0 + kk) * HID + q * 4)
            : make_float4(0.f, 0.f, 0.f, 0.f);
    }
}

__global__ void __launch_bounds__(256) k_gemm1(const float* __restrict__ X,
                                               const float* __restrict__ W) {
    __shared__ uint32_t As[32][132];   // [kk][row] tf32 bits, pad 4
    __shared__ uint32_t Bs[32][68];    // [kk][col] tf32 bits, pad 4

    const int row0 = blockIdx.x * 128;
    const int tid  = threadIdx.x;
    const int lane = tid & 31;
    const int wid  = tid >> 5;
    const int wm   = wid & 3;
    const int wn   = wid >> 2;
    const int g    = lane >> 2;
    const int q4   = lane & 3;

    float acc[2][4][4];
#pragma unroll
    for (int tm = 0; tm < 2; tm++)
#pragma unroll
        for (int tn = 0; tn < 4; tn++)
#pragma unroll
            for (int j = 0; j < 4; j++) acc[tm][tn][j] = 0.0f;

    float4 aR[4];
    float4 bR[2];
    g1_load(X, W, row0, 0, tid, aR, bR);

    const int NT = (INCH + 31) / 32;    // 16 tiles
    for (int kt = 0; kt < NT; kt++) {
        // store staged regs -> smem (with tf32 convert)
#pragma unroll
        for (int n = 0; n < 4; n++) {
            int i = tid + n * 256;
            int r = i >> 3, q = i & 7;
            As[q * 4 + 0][r] = f2tf32(aR[n].x);
            As[q * 4 + 1][r] = f2tf32(aR[n].y);
            As[q * 4 + 2][r] = f2tf32(aR[n].z);
            As[q * 4 + 3][r] = f2tf32(aR[n].w);
        }
#pragma unroll
        for (int n = 0; n < 2; n++) {
            int i = tid + n * 256;
            int kk = i >> 4, q = i & 15;
            Bs[kk][q * 4 + 0] = f2tf32(bR[n].x);
            Bs[kk][q * 4 + 1] = f2tf32(bR[n].y);
            Bs[kk][q * 4 + 2] = f2tf32(bR[n].z);
            Bs[kk][q * 4 + 3] = f2tf32(bR[n].w);
        }
        __syncthreads();

        // prefetch next tile into regs (overlaps with MMA below)
        if (kt + 1 < NT) g1_load(X, W, row0, (kt + 1) * 32, tid, aR, bR);

#pragma unroll
        for (int ks = 0; ks < 4; ks++) {
            const int kk = ks * 8 + q4;
            uint32_t a[2][4];
#pragma unroll
            for (int tm = 0; tm < 2; tm++) {
                int r = wm * 32 + tm * 16 + g;
                a[tm][0] = As[kk][r];
                a[tm][1] = As[kk][r + 8];
                a[tm][2] = As[kk + 4][r];
                a[tm][3] = As[kk + 4][r + 8];
            }
            uint32_t b[4][2];
#pragma unroll
            for (int tn = 0; tn < 4; tn++) {
                int c = wn * 32 + tn * 8 + g;
                b[tn][0] = Bs[kk][c];
                b[tn][1] = Bs[kk + 4][c];
            }
#pragma unroll
            for (int tm = 0; tm < 2; tm++)
#pragma unroll
                for (int tn = 0; tn < 4; tn++)
                    mma_tf32(acc[tm][tn], a[tm], b[tn]);
        }
        __syncthreads();
    }

#pragma unroll
    for (int tm = 0; tm < 2; tm++) {
#pragma unroll
        for (int tn = 0; tn < 4; tn++) {
            int c = wn * 32 + tn * 8 + q4 * 2;
            int r = row0 + wm * 32 + tm * 16 + g;
            if (r < NN)
                *reinterpret_cast<float2*>(&g_XW[(size_t)r * HID + c]) =
                    make_float2(acc[tm][tn][0], acc[tm][tn][1]);
            if (r + 8 < NN)
                *reinterpret_cast<float2*>(&g_XW[(size_t)(r + 8) * HID + c]) =
                    make_float2(acc[tm][tn][2], acc[tm][tn][3]);
        }
    }
}

// ---------------- layer-1 aggregation: warp/node, broadcast epk, unroll-4 ----------------
__global__ void k_agg1(const float* __restrict__ bcons) {
    int node = (blockIdx.x * blockDim.x + threadIdx.x) >> 5;
    int lane = threadIdx.x & 31;
    if (node >= NN) return;
    const int beg = g_off[node];
    const int end = g_off[node + 1];

    const float2* __restrict__ xw = reinterpret_cast<const float2*>(g_XW);
    float dd = g_dinv[node]; dd *= dd;
    float2 v0 = xw[(size_t)node * 32 + lane];
    float ax = dd * v0.x, ay = dd * v0.y;

    int i = beg;
    for (; i + 4 <= end; i += 4) {
        int2 e0 = g_epk[i + 0];
        int2 e1 = g_epk[i + 1];
        int2 e2 = g_epk[i + 2];
        int2 e3 = g_epk[i + 3];
        float2 p0 = xw[(size_t)e0.x * 32 + lane];
        float2 p1 = xw[(size_t)e1.x * 32 + lane];
        float2 p2 = xw[(size_t)e2.x * 32 + lane];
        float2 p3 = xw[(size_t)e3.x * 32 + lane];
        float w0 = __int_as_float(e0.y);
        float w1 = __int_as_float(e1.y);
        float w2 = __int_as_float(e2.y);
        float w3 = __int_as_float(e3.y);
        ax += w0 * p0.x; ay += w0 * p0.y;
        ax += w1 * p1.x; ay += w1 * p1.y;
        ax += w2 * p2.x; ay += w2 * p2.y;
        ax += w3 * p3.x; ay += w3 * p3.y;
    }
    for (; i < end; i++) {
        int2 e = g_epk[i];
        float2 p = xw[(size_t)e.x * 32 + lane];
        float w = __int_as_float(e.y);
        ax += w * p.x; ay += w * p.y;
    }

    float2 b = reinterpret_cast<const float2*>(bcons)[lane];
    float2 h = make_float2(fmaxf(ax + b.x, 0.0f), fmaxf(ay + b.y, 0.0f));
    reinterpret_cast<float2*>(g_H)[(size_t)node * 32 + lane] = h;
}

// ---------------- GEMM2: G = H @ W_cls  [100000 x 64] @ [64 x 40] ----------------
__global__ void __launch_bounds__(320) k_gemm2(const float* __restrict__ Wc) {
    __shared__ float Hs[64][65];
    __shared__ float Ws[64][40];

    const int row0 = blockIdx.x * 64;
    const int tid  = threadIdx.x;

    for (int i = tid; i < 64 * 64; i += 320) {
        int r = i >> 6, k = i & 63;
        int gr = row0 + r;
        Hs[r][k] = (gr < NN) ? g_H[(size_t)gr * HID + k] : 0.0f;
    }
    for (int i = tid; i < 64 * 40; i += 320) {
        int k = i / 40, c = i - k * 40;
        Ws[k][c] = Wc[(size_t)k * OUTC + c];
    }
    __syncthreads();

    const int r = tid / 40;
    const int c = tid - r * 40;
    float acc[8];
#pragma unroll
    for (int j = 0; j < 8; j++) acc[j] = 0.0f;

#pragma unroll
    for (int k = 0; k < 64; k++) {
        float w = Ws[k][c];
#pragma unroll
        for (int j = 0; j < 8; j++) acc[j] += Hs[r + j * 8][k] * w;
    }
#pragma unroll
    for (int j = 0; j < 8; j++) {
        int gr = row0 + r + j * 8;
        if (gr < NN) g_G[(size_t)gr * OUTC + c] = acc[j];
    }
}

// ---------------- layer-2 aggregation: warp/node, 20-lane float2 payload ----------------
__global__ void k_agg2(float* __restrict__ out, const float* __restrict__ bcls) {
    int node = (blockIdx.x * blockDim.x + threadIdx.x) >> 5;
    int lane = threadIdx.x & 31;
    if (node >= NN) return;
    const int beg = g_off[node];
    const int end = g_off[node + 1];

    const int cl = (lane < 20) ? lane : 0;   // lanes 20-31 duplicate lane 0 (discarded)
    const float2* __restrict__ G2 = reinterpret_cast<const float2*>(g_G);

    float dd = g_dinv[node]; dd *= dd;
    float2 v0 = G2[(size_t)node * 20 + cl];
    float ax = dd * v0.x, ay = dd * v0.y;

    int i = beg;
    for (; i + 4 <= end; i += 4) {
        int2 e0 = g_epk[i + 0];
        int2 e1 = g_epk[i + 1];
        int2 e2 = g_epk[i + 2];
        int2 e3 = g_epk[i + 3];
        float2 p0 = G2[(size_t)e0.x * 20 + cl];
        float2 p1 = G2[(size_t)e1.x * 20 + cl];
        float2 p2 = G2[(size_t)e2.x * 20 + cl];
        float2 p3 = G2[(size_t)e3.x * 20 + cl];
        float w0 = __int_as_float(e0.y);
        float w1 = __int_as_float(e1.y);
        float w2 = __int_as_float(e2.y);
        float w3 = __int_as_float(e3.y);
        ax += w0 * p0.x; ay += w0 * p0.y;
        ax += w1 * p1.x; ay += w1 * p1.y;
        ax += w2 * p2.x; ay += w2 * p2.y;
        ax += w3 * p3.x; ay += w3 * p3.y;
    }
    for (; i < end; i++) {
        int2 e = g_epk[i];
        float2 p = G2[(size_t)e.x * 20 + cl];
        float w = __int_as_float(e.y);
        ax += w * p.x; ay += w * p.y;
    }

    if (lane < 20) {
        float2 b = reinterpret_cast<const float2*>(bcls)[lane];
        reinterpret_cast<float2*>(out)[(size_t)node * 20 + lane] =
            make_float2(ax + b.x, ay + b.y);
    }
}

// ---------------- launch ----------------
extern "C" void kernel_launch(void* const* d_in, const int* in_sizes, int n_in,
                              void* d_out, int out_size) {
    const float* x     = (const float*)d_in[0];
    const int*   ei    = (const int*)  d_in[1];
    const float* Wcons = (const float*)d_in[2];
    const float* bcons = (const float*)d_in[3];
    const float* Wcls  = (const float*)d_in[4];
    const float* bcls  = (const float*)d_in[5];
    const int E = in_sizes[1] / 2;
    const int* src = ei;
    const int* dst = ei + E;
    float* out = (float*)d_out;

    void* cntp = nullptr;
    cudaGetSymbolAddress(&cntp, g_cnt);
    cudaMemsetAsync(cntp, 0, NN * sizeof(int));
    k_count<<<(E + 255) / 256, 256>>>(dst, E);

    k_scan_block<<<NB, 256>>>();
    k_scan_tops <<<1, 512>>>();
    k_scan_add  <<<NB, 256>>>(E);
    k_fill      <<<(E + 255) / 256, 256>>>(src, dst, E);

    k_gemm1<<<(NN + 127) / 128, 256>>>(x, Wcons);
    k_agg1 <<<(NN * 32 + 255) / 256, 256>>>(bcons);

    k_gemm2<<<(NN + 63) / 64, 320>>>(Wcls);
    k_agg2 <<<(NN * 32 + 255) / 256, 256>>>(out, bcls);
}

// round 5
// speedup vs baseline: 2.4387x; 1.0786x over previous
#include <cuda_runtime.h>
#include <cuda_fp16.h>
#include <cstdint>

#define NN    100000
#define INCH  500
#define HID   64
#define OUTC  40
#define EMAX  3200000
#define NB    ((NN + 255) / 256)   // scan blocks = 391

// ---------------- scratch (device globals) ----------------
__device__ float   g_dinv[NN];
__device__ int     g_cnt[NN];
__device__ int     g_off[NN + 1];
__device__ int     g_cur[NN];
__device__ int     g_bsum[512];
__device__ int     g_bscan[512];
__device__ int2    g_epk[EMAX];                 // (src, bitcast(weight)) grouped by dst
__device__ __half2 g_XWh[(size_t)NN * 32];      // x @ W_cons, fp16 pairs
__device__ float   g_H [(size_t)NN * HID];      // relu(agg1 + b_cons), fp32
__device__ __half2 g_Gh[(size_t)NN * 20];       // H @ W_cls, fp16 pairs

// ---------------- degree count ----------------
__global__ void k_count(const int* __restrict__ dst, int E) {
    int e = blockIdx.x * blockDim.x + threadIdx.x;
    if (e < E) atomicAdd(&g_cnt[dst[e]], 1);
}

// ---------------- 2-level exclusive scan over g_cnt -> g_off (dinv fused) ----------------
__global__ void k_scan_block() {
    __shared__ int sh[256];
    int b = blockIdx.x, t = threadIdx.x;
    int i = b * 256 + t;
    int v = (i < NN) ? g_cnt[i] : 0;
    if (i < NN) g_dinv[i] = rsqrtf((float)(v + 1));   // +1 self loop
    int x = v;
    sh[t] = x; __syncthreads();
#pragma unroll
    for (int d = 1; d < 256; d <<= 1) {
        int y = (t >= d) ? sh[t - d] : 0;
        __syncthreads();
        x += y; sh[t] = x;
        __syncthreads();
    }
    if (i < NN) g_off[i] = x - v;
    if (t == 255) g_bsum[b] = x;
}
__global__ void k_scan_tops() {
    __shared__ int sh[512];
    int t = threadIdx.x;
    int v = (t < NB) ? g_bsum[t] : 0;
    int x = v;
    sh[t] = x; __syncthreads();
#pragma unroll
    for (int d = 1; d < 512; d <<= 1) {
        int y = (t >= d) ? sh[t - d] : 0;
        __syncthreads();
        x += y; sh[t] = x;
        __syncthreads();
    }
    if (t < NB) g_bscan[t] = x - v;
}
__global__ void k_scan_add(int E) {
    int i = blockIdx.x * blockDim.x + threadIdx.x;
    if (i < NN) {
        g_off[i] += g_bscan[i >> 8];
        g_cur[i] = 0;
    }
    if (i == 0) g_off[NN] = E;
}

// ---------------- CSR fill: group edges by dst ----------------
__global__ void k_fill(const int* __restrict__ src, const int* __restrict__ dst, int E) {
    int e = blockIdx.x * blockDim.x + threadIdx.x;
    if (e >= E) return;
    int s = src[e];
    int d = dst[e];
    int pos = g_off[d] + atomicAdd(&g_cur[d], 1);
    g_epk[pos] = make_int2(s, __float_as_int(g_dinv[s] * g_dinv[d]));
}

// ---------------- GEMM1 (tf32 tensor cores, sw-pipelined): XWh = x @ W_cons ----------------
__device__ __forceinline__ uint32_t f2tf32(float f) {
    uint32_t r;
    asm("cvt.rna.tf32.f32 %0, %1;" : "=r"(r) : "f"(f));
    return r;
}
__device__ __forceinline__ void mma_tf32(float* d, const uint32_t* a, const uint32_t* b) {
    asm volatile(
        "mma.sync.aligned.m16n8k8.row.col.f32.tf32.tf32.f32 "
        "{%0,%1,%2,%3}, {%4,%5,%6,%7}, {%8,%9}, {%0,%1,%2,%3};"
        : "+f"(d[0]), "+f"(d[1]), "+f"(d[2]), "+f"(d[3])
        : "r"(a[0]), "r"(a[1]), "r"(a[2]), "r"(a[3]), "r"(b[0]), "r"(b[1]));
}

__device__ __forceinline__ void g1_load(const float* __restrict__ X,
                                        const float* __restrict__ W,
                                        int row0, int k0, int tid,
                                        float4 aR[4], float4 bR[2]) {
    const int kq = (INCH - k0 >= 32) ? 8 : (INCH - k0) / 4;   // valid float4s along k (8 or 5)
#pragma unroll
    for (int n = 0; n < 4; n++) {
        int i = tid + n * 256;
        int r = i >> 3, q = i & 7;
        int gr = row0 + r;
        aR[n] = (gr < NN && q < kq)
            ? *reinterpret_cast<const float4*>(X + (size_t)gr * INCH + k0 + q * 4)
            : make_float4(0.f, 0.f, 0.f, 0.f);
    }
#pragma unroll
    for (int n = 0; n < 2; n++) {
        int i = tid + n * 256;
        int kk = i >> 4, q = i & 15;
        bR[n] = (k0 + kk < INCH)
            ? *reinterpret_cast<const float4*>(W + (size_t)(k0 + kk) * HID + q * 4)
            : make_float4(0.f, 0.f, 0.f, 0.f);
    }
}

__global__ void __launch_bounds__(256) k_gemm1(const float* __restrict__ X,
                                               const float* __restrict__ W) {
    __shared__ uint32_t As[32][132];
    __shared__ uint32_t Bs[32][68];

    const int row0 = blockIdx.x * 128;
    const int tid  = threadIdx.x;
    const int lane = tid & 31;
    const int wid  = tid >> 5;
    const int wm   = wid & 3;
    const int wn   = wid >> 2;
    const int g    = lane >> 2;
    const int q4   = lane & 3;

    float acc[2][4][4];
#pragma unroll
    for (int tm = 0; tm < 2; tm++)
#pragma unroll
        for (int tn = 0; tn < 4; tn++)
#pragma unroll
            for (int j = 0; j < 4; j++) acc[tm][tn][j] = 0.0f;

    float4 aR[4];
    float4 bR[2];
    g1_load(X, W, row0, 0, tid, aR, bR);

    const int NT = (INCH + 31) / 32;
    for (int kt = 0; kt < NT; kt++) {
#pragma unroll
        for (int n = 0; n < 4; n++) {
            int i = tid + n * 256;
            int r = i >> 3, q = i & 7;
            As[q * 4 + 0][r] = f2tf32(aR[n].x);
            As[q * 4 + 1][r] = f2tf32(aR[n].y);
            As[q * 4 + 2][r] = f2tf32(aR[n].z);
            As[q * 4 + 3][r] = f2tf32(aR[n].w);
        }
#pragma unroll
        for (int n = 0; n < 2; n++) {
            int i = tid + n * 256;
            int kk = i >> 4, q = i & 15;
            Bs[kk][q * 4 + 0] = f2tf32(bR[n].x);
            Bs[kk][q * 4 + 1] = f2tf32(bR[n].y);
            Bs[kk][q * 4 + 2] = f2tf32(bR[n].z);
            Bs[kk][q * 4 + 3] = f2tf32(bR[n].w);
        }
        __syncthreads();

        if (kt + 1 < NT) g1_load(X, W, row0, (kt + 1) * 32, tid, aR, bR);

#pragma unroll
        for (int ks = 0; ks < 4; ks++) {
            const int kk = ks * 8 + q4;
            uint32_t a[2][4];
#pragma unroll
            for (int tm = 0; tm < 2; tm++) {
                int r = wm * 32 + tm * 16 + g;
                a[tm][0] = As[kk][r];
                a[tm][1] = As[kk][r + 8];
                a[tm][2] = As[kk + 4][r];
                a[tm][3] = As[kk + 4][r + 8];
            }
            uint32_t b[4][2];
#pragma unroll
            for (int tn = 0; tn < 4; tn++) {
                int c = wn * 32 + tn * 8 + g;
                b[tn][0] = Bs[kk][c];
                b[tn][1] = Bs[kk + 4][c];
            }
#pragma unroll
            for (int tm = 0; tm < 2; tm++)
#pragma unroll
                for (int tn = 0; tn < 4; tn++)
                    mma_tf32(acc[tm][tn], a[tm], b[tn]);
        }
        __syncthreads();
    }

    // epilogue: write fp16 pairs (cols q4*2, q4*2+1 adjacent -> one half2)
#pragma unroll
    for (int tm = 0; tm < 2; tm++) {
#pragma unroll
        for (int tn = 0; tn < 4; tn++) {
            int c2 = (wn * 32 + tn * 8 + q4 * 2) >> 1;
            int r = row0 + wm * 32 + tm * 16 + g;
            if (r < NN)
                g_XWh[(size_t)r * 32 + c2] = __floats2half2_rn(acc[tm][tn][0], acc[tm][tn][1]);
            if (r + 8 < NN)
                g_XWh[(size_t)(r + 8) * 32 + c2] = __floats2half2_rn(acc[tm][tn][2], acc[tm][tn][3]);
        }
    }
}

// ---------------- layer-1 aggregation: warp/node, fp16 gathers, fused bias+relu ----------------
__global__ void k_agg1(const float* __restrict__ bcons) {
    int node = (blockIdx.x * blockDim.x + threadIdx.x) >> 5;
    int lane = threadIdx.x & 31;
    if (node >= NN) return;
    const int beg = g_off[node];
    const int end = g_off[node + 1];

    float dd = g_dinv[node]; dd *= dd;
    float2 v0 = __half22float2(g_XWh[(size_t)node * 32 + lane]);
    float ax = dd * v0.x, ay = dd * v0.y;

    int i = beg;
    for (; i + 4 <= end; i += 4) {
        int2 e0 = g_epk[i + 0];
        int2 e1 = g_epk[i + 1];
        int2 e2 = g_epk[i + 2];
        int2 e3 = g_epk[i + 3];
        float2 p0 = __half22float2(g_XWh[(size_t)e0.x * 32 + lane]);
        float2 p1 = __half22float2(g_XWh[(size_t)e1.x * 32 + lane]);
        float2 p2 = __half22float2(g_XWh[(size_t)e2.x * 32 + lane]);
        float2 p3 = __half22float2(g_XWh[(size_t)e3.x * 32 + lane]);
        float w0 = __int_as_float(e0.y);
        float w1 = __int_as_float(e1.y);
        float w2 = __int_as_float(e2.y);
        float w3 = __int_as_float(e3.y);
        ax += w0 * p0.x; ay += w0 * p0.y;
        ax += w1 * p1.x; ay += w1 * p1.y;
        ax += w2 * p2.x; ay += w2 * p2.y;
        ax += w3 * p3.x; ay += w3 * p3.y;
    }
    for (; i < end; i++) {
        int2 e = g_epk[i];
        float2 p = __half22float2(g_XWh[(size_t)e.x * 32 + lane]);
        float w = __int_as_float(e.y);
        ax += w * p.x; ay += w * p.y;
    }

    float2 b = reinterpret_cast<const float2*>(bcons)[lane];
    float2 h = make_float2(fmaxf(ax + b.x, 0.0f), fmaxf(ay + b.y, 0.0f));
    reinterpret_cast<float2*>(g_H)[(size_t)node * 32 + lane] = h;
}

// ---------------- GEMM2: Gh = H @ W_cls  [100000 x 64] @ [64 x 40] ----------------
__global__ void __launch_bounds__(320) k_gemm2(const float* __restrict__ Wc) {
    __shared__ float Hs[64][65];
    __shared__ float Ws[64][40];   // reused as G staging after compute

    const int row0 = blockIdx.x * 64;
    const int tid  = threadIdx.x;

    for (int i = tid; i < 64 * 64; i += 320) {
        int r = i >> 6, k = i & 63;
        int gr = row0 + r;
        Hs[r][k] = (gr < NN) ? g_H[(size_t)gr * HID + k] : 0.0f;
    }
    for (int i = tid; i < 64 * 40; i += 320) {
        int k = i / 40, c = i - k * 40;
        Ws[k][c] = Wc[(size_t)k * OUTC + c];
    }
    __syncthreads();

    const int r = tid / 40;
    const int c = tid - r * 40;
    float acc[8];
#pragma unroll
    for (int j = 0; j < 8; j++) acc[j] = 0.0f;

#pragma unroll
    for (int k = 0; k < 64; k++) {
        float w = Ws[k][c];
#pragma unroll
        for (int j = 0; j < 8; j++) acc[j] += Hs[r + j * 8][k] * w;
    }
    __syncthreads();   // everyone done reading Ws
#pragma unroll
    for (int j = 0; j < 8; j++) Ws[r + j * 8][c] = acc[j];   // stage G tile
    __syncthreads();

    // write half2, coalesced: 64 rows x 20 half2 = 1280
    for (int i = tid; i < 64 * 20; i += 320) {
        int rr = i / 20, c2 = i - rr * 20;
        int gr = row0 + rr;
        if (gr < NN)
            g_Gh[(size_t)gr * 20 + c2] = __floats2half2_rn(Ws[rr][c2 * 2], Ws[rr][c2 * 2 + 1]);
    }
}

// ---------------- layer-2 aggregation: warp/node, fp16 gathers, fused b_cls ----------------
__global__ void k_agg2(float* __restrict__ out, const float* __restrict__ bcls) {
    int node = (blockIdx.x * blockDim.x + threadIdx.x) >> 5;
    int lane = threadIdx.x & 31;
    if (node >= NN) return;
    const int beg = g_off[node];
    const int end = g_off[node + 1];

    const int cl = (lane < 20) ? lane : 0;

    float dd = g_dinv[node]; dd *= dd;
    float2 v0 = __half22float2(g_Gh[(size_t)node * 20 + cl]);
    float ax = dd * v0.x, ay = dd * v0.y;

    int i = beg;
    for (; i + 4 <= end; i += 4) {
        int2 e0 = g_epk[i + 0];
        int2 e1 = g_epk[i + 1];
        int2 e2 = g_epk[i + 2];
        int2 e3 = g_epk[i + 3];
        float2 p0 = __half22float2(g_Gh[(size_t)e0.x * 20 + cl]);
        float2 p1 = __half22float2(g_Gh[(size_t)e1.x * 20 + cl]);
        float2 p2 = __half22float2(g_Gh[(size_t)e2.x * 20 + cl]);
        float2 p3 = __half22float2(g_Gh[(size_t)e3.x * 20 + cl]);
        float w0 = __int_as_float(e0.y);
        float w1 = __int_as_float(e1.y);
        float w2 = __int_as_float(e2.y);
        float w3 = __int_as_float(e3.y);
        ax += w0 * p0.x; ay += w0 * p0.y;
        ax += w1 * p1.x; ay += w1 * p1.y;
        ax += w2 * p2.x; ay += w2 * p2.y;
        ax += w3 * p3.x; ay += w3 * p3.y;
    }
    for (; i < end; i++) {
        int2 e = g_epk[i];
        float2 p = __half22float2(g_Gh[(size_t)e.x * 20 + cl]);
        float w = __int_as_float(e.y);
        ax += w * p.x; ay += w * p.y;
    }

    if (lane < 20) {
        float2 b = reinterpret_cast<const float2*>(bcls)[lane];
        reinterpret_cast<float2*>(out)[(size_t)node * 20 + lane] =
            make_float2(ax + b.x, ay + b.y);
    }
}

// ---------------- launch ----------------
extern "C" void kernel_launch(void* const* d_in, const int* in_sizes, int n_in,
                              void* d_out, int out_size) {
    const float* x     = (const float*)d_in[0];
    const int*   ei    = (const int*)  d_in[1];
    const float* Wcons = (const float*)d_in[2];
    const float* bcons = (const float*)d_in[3];
    const float* Wcls  = (const float*)d_in[4];
    const float* bcls  = (const float*)d_in[5];
    const int E = in_sizes[1] / 2;
    const int* src = ei;
    const int* dst = ei + E;
    float* out = (float*)d_out;

    // fork: gemm1 (x, W_cons only) runs parallel to the CSR build (edge_index only)
    cudaStream_t s2;
    cudaStreamCreateWithFlags(&s2, cudaStreamNonBlocking);
    cudaEvent_t evF, evJ;
    cudaEventCreateWithFlags(&evF, cudaEventDisableTiming);
    cudaEventCreateWithFlags(&evJ, cudaEventDisableTiming);

    cudaEventRecord(evF, 0);
    cudaStreamWaitEvent(s2, evF, 0);
    k_gemm1<<<(NN + 127) / 128, 256, 0, s2>>>(x, Wcons);
    cudaEventRecord(evJ, s2);

    // main stream: degree + CSR build
    void* cntp = nullptr;
    cudaGetSymbolAddress(&cntp, g_cnt);
    cudaMemsetAsync(cntp, 0, NN * sizeof(int));
    k_count<<<(E + 255) / 256, 256>>>(dst, E);
    k_scan_block<<<NB, 256>>>();
    k_scan_tops <<<1, 512>>>();
    k_scan_add  <<<NB, 256>>>(E);
    k_fill      <<<(E + 255) / 256, 256>>>(src, dst, E);

    // join, then layer 1 aggregation
    cudaStreamWaitEvent(0, evJ, 0);
    k_agg1<<<(NN * 32 + 255) / 256, 256>>>(bcons);

    // layer 2
    k_gemm2<<<(NN + 63) / 64, 320>>>(Wcls);
    k_agg2 <<<(NN * 32 + 255) / 256, 256>>>(out, bcls);
}

// round 6
// speedup vs baseline: 2.5119x; 1.0300x over previous
#include <cuda_runtime.h>
#include <cuda_fp16.h>
#include <cstdint>

#define NN    100000
#define INCH  500
#define HID   64
#define OUTC  40
#define EMAX  3200000
#define NB    ((NN + 255) / 256)   // scan blocks = 391

// ---------------- scratch (device globals) ----------------
__device__ float   g_dinv[NN];
__device__ int     g_cnt[NN];
__device__ int     g_off[NN];       // per-block exclusive scan (bscan NOT folded in)
__device__ int     g_cur[NN];
__device__ int     g_bsum[512];
__device__ int     g_bscan[512];
__device__ int2    g_epk[EMAX];                 // (src, bitcast(weight)) grouped by dst
__device__ __half2 g_XWh[(size_t)NN * 32];      // x @ W_cons, fp16 pairs
__device__ float   g_H [(size_t)NN * HID];      // relu(agg1 + b_cons), fp32
__device__ __half2 g_Gh[(size_t)NN * 20];       // H @ W_cls, fp16 pairs

// final CSR offset of node i (bscan folded on the fly)
__device__ __forceinline__ int csr_off(int i, int E) {
    return (i >= NN) ? E : (g_off[i] + g_bscan[i >> 8]);
}

// ---------------- degree count ----------------
__global__ void k_count(const int* __restrict__ dst, int E) {
    int e = blockIdx.x * blockDim.x + threadIdx.x;
    if (e < E) atomicAdd(&g_cnt[dst[e]], 1);
}

// ---------------- per-block exclusive scan over g_cnt (dinv fused) ----------------
__global__ void k_scan_block() {
    __shared__ int sh[256];
    int b = blockIdx.x, t = threadIdx.x;
    int i = b * 256 + t;
    int v = (i < NN) ? g_cnt[i] : 0;
    if (i < NN) g_dinv[i] = rsqrtf((float)(v + 1));   // +1 self loop
    int x = v;
    sh[t] = x; __syncthreads();
#pragma unroll
    for (int d = 1; d < 256; d <<= 1) {
        int y = (t >= d) ? sh[t - d] : 0;
        __syncthreads();
        x += y; sh[t] = x;
        __syncthreads();
    }
    if (i < NN) g_off[i] = x - v;
    if (t == 255) g_bsum[b] = x;
}
__global__ void k_scan_tops() {
    __shared__ int sh[512];
    int t = threadIdx.x;
    int v = (t < NB) ? g_bsum[t] : 0;
    int x = v;
    sh[t] = x; __syncthreads();
#pragma unroll
    for (int d = 1; d < 512; d <<= 1) {
        int y = (t >= d) ? sh[t - d] : 0;
        __syncthreads();
        x += y; sh[t] = x;
        __syncthreads();
    }
    if (t < NB) g_bscan[t] = x - v;
}

// ---------------- CSR fill: group edges by dst ----------------
__global__ void k_fill(const int* __restrict__ src, const int* __restrict__ dst, int E) {
    int e = blockIdx.x * blockDim.x + threadIdx.x;
    if (e >= E) return;
    int s = src[e];
    int d = dst[e];
    int pos = g_off[d] + g_bscan[d >> 8] + atomicAdd(&g_cur[d], 1);
    g_epk[pos] = make_int2(s, __float_as_int(g_dinv[s] * g_dinv[d]));
}

// ---------------- GEMM1 (tf32 tensor cores, sw-pipelined): XWh = x @ W_cons ----------------
__device__ __forceinline__ uint32_t f2tf32(float f) {
    uint32_t r;
    asm("cvt.rna.tf32.f32 %0, %1;" : "=r"(r) : "f"(f));
    return r;
}
__device__ __forceinline__ void mma_tf32(float* d, const uint32_t* a, const uint32_t* b) {
    asm volatile(
        "mma.sync.aligned.m16n8k8.row.col.f32.tf32.tf32.f32 "
        "{%0,%1,%2,%3}, {%4,%5,%6,%7}, {%8,%9}, {%0,%1,%2,%3};"
        : "+f"(d[0]), "+f"(d[1]), "+f"(d[2]), "+f"(d[3])
        : "r"(a[0]), "r"(a[1]), "r"(a[2]), "r"(a[3]), "r"(b[0]), "r"(b[1]));
}

__device__ __forceinline__ void g1_load(const float* __restrict__ X,
                                        const float* __restrict__ W,
                                        int row0, int k0, int tid,
                                        float4 aR[4], float4 bR[2]) {
    const int kq = (INCH - k0 >= 32) ? 8 : (INCH - k0) / 4;
#pragma unroll
    for (int n = 0; n < 4; n++) {
        int i = tid + n * 256;
        int r = i >> 3, q = i & 7;
        int gr = row0 + r;
        aR[n] = (gr < NN && q < kq)
            ? *reinterpret_cast<const float4*>(X + (size_t)gr * INCH + k0 + q * 4)
            : make_float4(0.f, 0.f, 0.f, 0.f);
    }
#pragma unroll
    for (int n = 0; n < 2; n++) {
        int i = tid + n * 256;
        int kk = i >> 4, q = i & 15;
        bR[n] = (k0 + kk < INCH)
            ? *reinterpret_cast<const float4*>(W + (size_t)(k0 + kk) * HID + q * 4)
            : make_float4(0.f, 0.f, 0.f, 0.f);
    }
}

__global__ void __launch_bounds__(256) k_gemm1(const float* __restrict__ X,
                                               const float* __restrict__ W) {
    __shared__ uint32_t As[32][132];
    __shared__ uint32_t Bs[32][68];

    const int row0 = blockIdx.x * 128;
    const int tid  = threadIdx.x;
    const int lane = tid & 31;
    const int wid  = tid >> 5;
    const int wm   = wid & 3;
    const int wn   = wid >> 2;
    const int g    = lane >> 2;
    const int q4   = lane & 3;

    float acc[2][4][4];
#pragma unroll
    for (int tm = 0; tm < 2; tm++)
#pragma unroll
        for (int tn = 0; tn < 4; tn++)
#pragma unroll
            for (int j = 0; j < 4; j++) acc[tm][tn][j] = 0.0f;

    float4 aR[4];
    float4 bR[2];
    g1_load(X, W, row0, 0, tid, aR, bR);

    const int NT = (INCH + 31) / 32;
    for (int kt = 0; kt < NT; kt++) {
#pragma unroll
        for (int n = 0; n < 4; n++) {
            int i = tid + n * 256;
            int r = i >> 3, q = i & 7;
            As[q * 4 + 0][r] = f2tf32(aR[n].x);
            As[q * 4 + 1][r] = f2tf32(aR[n].y);
            As[q * 4 + 2][r] = f2tf32(aR[n].z);
            As[q * 4 + 3][r] = f2tf32(aR[n].w);
        }
#pragma unroll
        for (int n = 0; n < 2; n++) {
            int i = tid + n * 256;
            int kk = i >> 4, q = i & 15;
            Bs[kk][q * 4 + 0] = f2tf32(bR[n].x);
            Bs[kk][q * 4 + 1] = f2tf32(bR[n].y);
            Bs[kk][q * 4 + 2] = f2tf32(bR[n].z);
            Bs[kk][q * 4 + 3] = f2tf32(bR[n].w);
        }
        __syncthreads();

        if (kt + 1 < NT) g1_load(X, W, row0, (kt + 1) * 32, tid, aR, bR);

#pragma unroll
        for (int ks = 0; ks < 4; ks++) {
            const int kk = ks * 8 + q4;
            uint32_t a[2][4];
#pragma unroll
            for (int tm = 0; tm < 2; tm++) {
                int r = wm * 32 + tm * 16 + g;
                a[tm][0] = As[kk][r];
                a[tm][1] = As[kk][r + 8];
                a[tm][2] = As[kk + 4][r];
                a[tm][3] = As[kk + 4][r + 8];
            }
            uint32_t b[4][2];
#pragma unroll
            for (int tn = 0; tn < 4; tn++) {
                int c = wn * 32 + tn * 8 + g;
                b[tn][0] = Bs[kk][c];
                b[tn][1] = Bs[kk + 4][c];
            }
#pragma unroll
            for (int tm = 0; tm < 2; tm++)
#pragma unroll
                for (int tn = 0; tn < 4; tn++)
                    mma_tf32(acc[tm][tn], a[tm], b[tn]);
        }
        __syncthreads();
    }

#pragma unroll
    for (int tm = 0; tm < 2; tm++) {
#pragma unroll
        for (int tn = 0; tn < 4; tn++) {
            int c2 = (wn * 32 + tn * 8 + q4 * 2) >> 1;
            int r = row0 + wm * 32 + tm * 16 + g;
            if (r < NN)
                g_XWh[(size_t)r * 32 + c2] = __floats2half2_rn(acc[tm][tn][0], acc[tm][tn][1]);
            if (r + 8 < NN)
                g_XWh[(size_t)(r + 8) * 32 + c2] = __floats2half2_rn(acc[tm][tn][2], acc[tm][tn][3]);
        }
    }
}

// ---------------- layer-1 aggregation: warp/node, fp16 gathers, unroll-8 ----------------
__global__ void k_agg1(const float* __restrict__ bcons, int E) {
    int node = (blockIdx.x * blockDim.x + threadIdx.x) >> 5;
    int lane = threadIdx.x & 31;
    if (node >= NN) return;
    const int beg = csr_off(node, E);
    const int end = csr_off(node + 1, E);

    float dd = g_dinv[node]; dd *= dd;
    float2 v0 = __half22float2(g_XWh[(size_t)node * 32 + lane]);
    float ax = dd * v0.x, ay = dd * v0.y;

    int i = beg;
    for (; i + 8 <= end; i += 8) {
        int2 ee[8];
#pragma unroll
        for (int u = 0; u < 8; u++) ee[u] = g_epk[i + u];
        float2 pp[8];
#pragma unroll
        for (int u = 0; u < 8; u++) pp[u] = __half22float2(g_XWh[(size_t)ee[u].x * 32 + lane]);
#pragma unroll
        for (int u = 0; u < 8; u++) {
            float w = __int_as_float(ee[u].y);
            ax += w * pp[u].x;
            ay += w * pp[u].y;
        }
    }
    for (; i < end; i++) {
        int2 e = g_epk[i];
        float2 p = __half22float2(g_XWh[(size_t)e.x * 32 + lane]);
        float w = __int_as_float(e.y);
        ax += w * p.x; ay += w * p.y;
    }

    float2 b = reinterpret_cast<const float2*>(bcons)[lane];
    float2 h = make_float2(fmaxf(ax + b.x, 0.0f), fmaxf(ay + b.y, 0.0f));
    reinterpret_cast<float2*>(g_H)[(size_t)node * 32 + lane] = h;
}

// ---------------- GEMM2: Gh = H @ W_cls  [100000 x 64] @ [64 x 40] ----------------
__global__ void __launch_bounds__(320) k_gemm2(const float* __restrict__ Wc) {
    __shared__ float Hs[64][65];
    __shared__ float Ws[64][40];   // reused as G staging after compute

    const int row0 = blockIdx.x * 64;
    const int tid  = threadIdx.x;

    for (int i = tid; i < 64 * 64; i += 320) {
        int r = i >> 6, k = i & 63;
        int gr = row0 + r;
        Hs[r][k] = (gr < NN) ? g_H[(size_t)gr * HID + k] : 0.0f;
    }
    for (int i = tid; i < 64 * 40; i += 320) {
        int k = i / 40, c = i - k * 40;
        Ws[k][c] = Wc[(size_t)k * OUTC + c];
    }
    __syncthreads();

    const int r = tid / 40;
    const int c = tid - r * 40;
    float acc[8];
#pragma unroll
    for (int j = 0; j < 8; j++) acc[j] = 0.0f;

#pragma unroll
    for (int k = 0; k < 64; k++) {
        float w = Ws[k][c];
#pragma unroll
        for (int j = 0; j < 8; j++) acc[j] += Hs[r + j * 8][k] * w;
    }
    __syncthreads();
#pragma unroll
    for (int j = 0; j < 8; j++) Ws[r + j * 8][c] = acc[j];
    __syncthreads();

    for (int i = tid; i < 64 * 20; i += 320) {
        int rr = i / 20, c2 = i - rr * 20;
        int gr = row0 + rr;
        if (gr < NN)
            g_Gh[(size_t)gr * 20 + c2] = __floats2half2_rn(Ws[rr][c2 * 2], Ws[rr][c2 * 2 + 1]);
    }
}

// ---------------- layer-2 aggregation: warp/node, fp16 gathers, unroll-8 ----------------
__global__ void k_agg2(float* __restrict__ out, const float* __restrict__ bcls, int E) {
    int node = (blockIdx.x * blockDim.x + threadIdx.x) >> 5;
    int lane = threadIdx.x & 31;
    if (node >= NN) return;
    const int beg = csr_off(node, E);
    const int end = csr_off(node + 1, E);

    const int cl = (lane < 20) ? lane : 0;

    float dd = g_dinv[node]; dd *= dd;
    float2 v0 = __half22float2(g_Gh[(size_t)node * 20 + cl]);
    float ax = dd * v0.x, ay = dd * v0.y;

    int i = beg;
    for (; i + 8 <= end; i += 8) {
        int2 ee[8];
#pragma unroll
        for (int u = 0; u < 8; u++) ee[u] = g_epk[i + u];
        float2 pp[8];
#pragma unroll
        for (int u = 0; u < 8; u++) pp[u] = __half22float2(g_Gh[(size_t)ee[u].x * 20 + cl]);
#pragma unroll
        for (int u = 0; u < 8; u++) {
            float w = __int_as_float(ee[u].y);
            ax += w * pp[u].x;
            ay += w * pp[u].y;
        }
    }
    for (; i < end; i++) {
        int2 e = g_epk[i];
        float2 p = __half22float2(g_Gh[(size_t)e.x * 20 + cl]);
        float w = __int_as_float(e.y);
        ax += w * p.x; ay += w * p.y;
    }

    if (lane < 20) {
        float2 b = reinterpret_cast<const float2*>(bcls)[lane];
        reinterpret_cast<float2*>(out)[(size_t)node * 20 + lane] =
            make_float2(ax + b.x, ay + b.y);
    }
}

// ---------------- launch ----------------
extern "C" void kernel_launch(void* const* d_in, const int* in_sizes, int n_in,
                              void* d_out, int out_size) {
    const float* x     = (const float*)d_in[0];
    const int*   ei    = (const int*)  d_in[1];
    const float* Wcons = (const float*)d_in[2];
    const float* bcons = (const float*)d_in[3];
    const float* Wcls  = (const float*)d_in[4];
    const float* bcls  = (const float*)d_in[5];
    const int E = in_sizes[1] / 2;
    const int* src = ei;
    const int* dst = ei + E;
    float* out = (float*)d_out;

    cudaStream_t s2;
    cudaStreamCreateWithFlags(&s2, cudaStreamNonBlocking);
    cudaEvent_t evF, evJ;
    cudaEventCreateWithFlags(&evF, cudaEventDisableTiming);
    cudaEventCreateWithFlags(&evJ, cudaEventDisableTiming);

    // fork BEFORE gemm1 so the CSR chain runs in parallel with it
    cudaEventRecord(evF, 0);
    cudaStreamWaitEvent(s2, evF, 0);

    // main stream: gemm1 (kernel launch #0 — keeps agg1 at sample slot 5)
    k_gemm1<<<(NN + 127) / 128, 256>>>(x, Wcons);

    // s2: degree + CSR build (count=1, scan_block=2, scan_tops=3, fill=4)
    void* cntp = nullptr; cudaGetSymbolAddress(&cntp, g_cnt);
    void* curp = nullptr; cudaGetSymbolAddress(&curp, g_cur);
    cudaMemsetAsync(cntp, 0, NN * sizeof(int), s2);
    cudaMemsetAsync(curp, 0, NN * sizeof(int), s2);
    k_count     <<<(E + 255) / 256, 256, 0, s2>>>(dst, E);
    k_scan_block<<<NB, 256, 0, s2>>>();
    k_scan_tops <<<1, 512, 0, s2>>>();
    k_fill      <<<(E + 255) / 256, 256, 0, s2>>>(src, dst, E);
    cudaEventRecord(evJ, s2);

    // join, then layer 1 aggregation (kernel launch #5 — ncu target)
    cudaStreamWaitEvent(0, evJ, 0);
    k_agg1<<<(NN * 32 + 255) / 256, 256>>>(bcons, E);

    // layer 2
    k_gemm2<<<(NN + 63) / 64, 320>>>(Wcls);
    k_agg2 <<<(NN * 32 + 255) / 256, 256>>>(out, bcls, E);
}